// round 12
// baseline (speedup 1.0000x reference)
#include <cuda_runtime.h>
#include <cuda_bf16.h>
#include <cstdint>

#define Bb 4096
#define Tt 128
#define Ff 64
#define Hh 32

typedef unsigned long long u64;

// xz in gate-pair-interleaved u64 form: xzp[row][p] with
//   p in [0,32):  (z_i[p],    z_f[p])      = (z[p],    z[32+p])
//   p in [32,64): (z_g[p-32], z_o[p-32])   = (z[64+q], z[96+q])
__device__ u64 g_xzp[(size_t)Bb * Tt * 64];

// ---------- f32x2 packed helpers ----------
__device__ __forceinline__ u64 pk2(float lo, float hi) {
    u64 r; asm("mov.b64 %0, {%1, %2};" : "=l"(r) : "f"(lo), "f"(hi)); return r;
}
__device__ __forceinline__ void upk2(u64 v, float &lo, float &hi) {
    asm("mov.b64 {%0, %1}, %2;" : "=f"(lo), "=f"(hi) : "l"(v));
}
__device__ __forceinline__ u64 fma2(u64 a, u64 b, u64 c) {
    u64 d; asm("fma.rn.f32x2 %0, %1, %2, %3;" : "=l"(d) : "l"(a), "l"(b), "l"(c)); return d;
}
__device__ __forceinline__ u64 add2(u64 a, u64 b) {
    u64 d; asm("add.rn.f32x2 %0, %1, %2;" : "=l"(d) : "l"(a), "l"(b)); return d;
}

// ---------- cp.async helpers ----------
__device__ __forceinline__ void cpa16(void* dst, const void* src) {
    unsigned ds = (unsigned)__cvta_generic_to_shared(dst);
    asm volatile("cp.async.ca.shared.global [%0], [%1], 16;" :: "r"(ds), "l"(src));
}
__device__ __forceinline__ void cpa_commit() {
    asm volatile("cp.async.commit_group;");
}
template<int N> __device__ __forceinline__ void cpa_wait() {
    asm volatile("cp.async.wait_group %0;" :: "n"(N));
}

__device__ __forceinline__ float sigf(float x) {
    return __fdividef(1.0f, 1.0f + __expf(-x));
}
__device__ __forceinline__ float cellf(float zi, float zf, float zg, float zo, float &c) {
    float i = sigf(zi);
    float f = sigf(zf);
    float g = fmaxf(zg, 0.0f);
    float o = sigf(zo);
    c = fmaf(f, c, i * g);
    return o * fmaxf(c, 0.0f);
}

__device__ __forceinline__ unsigned short bf16bits(float f) {
    __nv_bfloat16 b = __float2bfloat16(f);
    return *reinterpret_cast<unsigned short*>(&b);
}
__device__ __forceinline__ float bf16val(unsigned short s) {
    __nv_bfloat16 b = *reinterpret_cast<__nv_bfloat16*>(&s);
    return __bfloat162float(b);
}

// mma.sync m16n8k16 bf16 -> f32 (sm_80+ PTX, works on sm_103 base target)
__device__ __forceinline__ void mma16816(float* d,
                                         uint32_t a0, uint32_t a1, uint32_t a2, uint32_t a3,
                                         uint32_t b0, uint32_t b1) {
    asm volatile("mma.sync.aligned.m16n8k16.row.col.f32.bf16.bf16.f32 "
                 "{%0,%1,%2,%3}, {%4,%5,%6,%7}, {%8,%9}, {%0,%1,%2,%3};"
                 : "+f"(d[0]), "+f"(d[1]), "+f"(d[2]), "+f"(d[3])
                 : "r"(a0), "r"(a1), "r"(a2), "r"(a3), "r"(b0), "r"(b1));
}

// SMEM layout for k_xz. bf16 rows padded to 72 elems (144B): conflict-free.
#define AS_HI 0
#define AS_LO 9216
#define BS_HI 18432
#define BS_LO 36864
#define SMX_TOTAL 55296

// =====================================================================
// Kernel 1: xz = x @ We + be via mma.sync bf16-split (3 terms).
// CTA = 64 rows x 128 gates x K=64, 128 threads (4 warps).
// Prep folded in: B-split computed per-CTA from We (L1/L2-resident),
// be read inline in the epilogue. Warp w: rows [16w,16w+16), 16 n-tiles.
// =====================================================================
__global__ __launch_bounds__(128) void k_xz(const float* __restrict__ x,
                                            const float* __restrict__ We,
                                            const float* __restrict__ be)
{
    extern __shared__ __align__(16) char sm[];
    const int tid = threadIdx.x;
    const int wid = tid >> 5;
    const int lane = tid & 31;
    const int g = lane >> 2, t = lane & 3;

    // --- build B hi/lo (Bt[n][k] = We[k][n]) directly into padded smem ---
    for (int i = tid; i < 1024; i += 128) {
        int n = i >> 3, grp = i & 7;
        unsigned short hi[8], lo[8];
#pragma unroll
        for (int j = 0; j < 8; j++) {
            float v = __ldg(We + (grp * 8 + j) * 128 + n);
            hi[j] = bf16bits(v);
            lo[j] = bf16bits(v - bf16val(hi[j]));
        }
        *(uint4*)(sm + BS_HI + n * 144 + grp * 16) = *(uint4*)hi;
        *(uint4*)(sm + BS_LO + n * 144 + grp * 16) = *(uint4*)lo;
    }
    // --- stage + split A tile (64 rows x 64 f32 -> bf16 hi/lo, padded) ---
    {
        const float4* xb = (const float4*)(x + (size_t)blockIdx.x * 64 * 64);
        for (int i = tid; i < 1024; i += 128) {
            int row = i >> 4, kq = i & 15;
            float4 v = __ldg(xb + i);
            float vs[4] = {v.x, v.y, v.z, v.w};
            unsigned short hi[4], lo[4];
#pragma unroll
            for (int j = 0; j < 4; j++) {
                hi[j] = bf16bits(vs[j]);
                lo[j] = bf16bits(vs[j] - bf16val(hi[j]));
            }
            *(uint2*)(sm + AS_HI + row * 144 + kq * 8) = *(uint2*)hi;
            *(uint2*)(sm + AS_LO + row * 144 + kq * 8) = *(uint2*)lo;
        }
    }
    __syncthreads();

    const int rowlo = wid * 16;
    const char* Ah = sm + AS_HI + (rowlo + g) * 144 + t * 4;
    const char* Al = sm + AS_LO + (rowlo + g) * 144 + t * 4;
    const char* Bh = sm + BS_HI + g * 144 + t * 4;
    const char* Bl = sm + BS_LO + g * 144 + t * 4;

    float acc[16][4];
#pragma unroll
    for (int j = 0; j < 16; j++)
#pragma unroll
        for (int q = 0; q < 4; q++) acc[j][q] = 0.0f;

#pragma unroll
    for (int ks = 0; ks < 4; ks++) {
        const int ko = ks * 32;                 // 16 bf16 = 32 bytes per k-step
        uint32_t ah0 = *(const uint32_t*)(Ah + ko);
        uint32_t ah1 = *(const uint32_t*)(Ah + ko + 1152);   // row+8
        uint32_t ah2 = *(const uint32_t*)(Ah + ko + 16);     // k+8
        uint32_t ah3 = *(const uint32_t*)(Ah + ko + 1152 + 16);
        uint32_t al0 = *(const uint32_t*)(Al + ko);
        uint32_t al1 = *(const uint32_t*)(Al + ko + 1152);
        uint32_t al2 = *(const uint32_t*)(Al + ko + 16);
        uint32_t al3 = *(const uint32_t*)(Al + ko + 1152 + 16);
#pragma unroll
        for (int j = 0; j < 16; j++) {
            const char* bh = Bh + j * 1152 + ko;
            const char* bl = Bl + j * 1152 + ko;
            uint32_t bh0 = *(const uint32_t*)bh;
            uint32_t bh1 = *(const uint32_t*)(bh + 16);
            uint32_t bl0 = *(const uint32_t*)bl;
            uint32_t bl1 = *(const uint32_t*)(bl + 16);
            mma16816(acc[j], ah0, ah1, ah2, ah3, bh0, bh1);   // hi*hi
            mma16816(acc[j], al0, al1, al2, al3, bh0, bh1);   // lo*hi
            mma16816(acc[j], ah0, ah1, ah2, ah3, bl0, bl1);   // hi*lo
        }
    }

    // ---- epilogue: pair gates (p, p+32) from tiles j and j+4, add be, store
    const size_t r0 = (size_t)blockIdx.x * 64 + rowlo + g;
    const size_t r1 = r0 + 8;
#pragma unroll
    for (int half = 0; half < 2; half++) {
#pragma unroll
        for (int jj = 0; jj < 4; jj++) {
            int j = half * 8 + jj;
            int p = half * 32 + jj * 8 + 2 * t;
            int a = half ? (p + 32) : p;        // gate base for pair p
            ulonglong2 bb;
            bb.x = pk2(__ldg(be + a),     __ldg(be + a + 32));
            bb.y = pk2(__ldg(be + a + 1), __ldg(be + a + 33));
            ulonglong2 s0, s1;
            s0.x = add2(pk2(acc[j][0], acc[j + 4][0]), bb.x);
            s0.y = add2(pk2(acc[j][1], acc[j + 4][1]), bb.y);
            s1.x = add2(pk2(acc[j][2], acc[j + 4][2]), bb.x);
            s1.y = add2(pk2(acc[j][3], acc[j + 4][3]), bb.y);
            *(ulonglong2*)&g_xzp[r0 * 64 + p] = s0;
            *(ulonglong2*)&g_xzp[r1 * 64 + p] = s1;
        }
    }
}

// =====================================================================
// Kernel 2: fused encoder + decoder + Dense(64).
// 128-thread CTAs = 2 INDEPENDENT 2-warp teams (named barriers, not
// __syncthreads, so teams don't couple). Wos shared by both teams ->
// 21KB/CTA; with carveout=100% the whole grid (1024 CTAs) is resident
// in one wave. Team structure identical to round 9 (known-good).
// =====================================================================
#define TEAM_BAR() asm volatile("bar.sync %0, 64;" :: "r"(team + 1) : "memory")

__global__ __launch_bounds__(128) void k_rnn(const float* __restrict__ Ue,
                                             const float* __restrict__ Ud,
                                             const float* __restrict__ Wd,
                                             const float* __restrict__ bd,
                                             const float* __restrict__ Wout,
                                             const float* __restrict__ bout,
                                             float* __restrict__ y)
{
    __shared__ __align__(16) u64 Wos[32 * 32];        // 8KB, shared by teams
    __shared__ __align__(16) u64 ring[2][2][4][64];   // 8KB [team][tw][slot][idx]
    __shared__ __align__(16) u64 hds[2][2][2][32];    // 2KB [team][buf][tw][kk]
    __shared__ __align__(16) u64 px[2][2][3][32];     // 3KB [team][srcw][v][lane]

    const int tid = threadIdx.x;
    const int lane = tid & 31;
    const int wid = tid >> 5;
    const int team = wid >> 1;
    const int tw = wid & 1;
    const int otw = tw ^ 1;
    const int row = blockIdx.x * 4 + team * 2 + tw;   // row this warp finalizes
    const int base = tw * 16;                         // owned kk range

    for (int i = tid; i < 32 * 32; i += 128) {
        int kk = i >> 5, l = i & 31;
        Wos[i] = pk2(__ldg(Wout + kk * 64 + l), __ldg(Wout + kk * 64 + 32 + l));
    }

    // ---------------- encoder ----------------
    u64 wif[16], wgo[16];
#pragma unroll
    for (int j = 0; j < 16; j++) {
        const float* u = Ue + (base + j) * 128;
        wif[j] = pk2(__ldg(u + lane),      __ldg(u + 32 + lane));
        wgo[j] = pk2(__ldg(u + 64 + lane), __ldg(u + 96 + lane));
    }

    const u64* xzr = g_xzp + (size_t)row * 128 * 64;
#pragma unroll
    for (int p = 0; p < 3; p++) {
        cpa16(&ring[team][tw][p][lane * 2], xzr + (size_t)p * 64 + lane * 2);
        cpa_commit();
    }

    hds[team][0][tw][lane] = 0ULL;
    hds[team][1][tw][lane] = 0ULL;
    cpa_wait<2>();
    __syncthreads();   // one-time: Wos visible to all; h-bufs init

    float h = 0.f, cc = 0.f;

    for (int t = 0; t < 128; t++) {
        const int cb = t & 1;
        const u64* hcm = hds[team][cb][tw];
        const u64* hco = hds[team][cb][otw];
        const u64* slot = ring[team][tw][t & 3];

        u64 aifm = slot[lane], agom = slot[32 + lane];
        u64 aifo = 0ULL, agoo = 0ULL;

        if (t < 125) {
            cpa16(&ring[team][tw][(t + 3) & 3][lane * 2],
                  xzr + (size_t)(t + 3) * 64 + lane * 2);
            cpa_commit();
        }

#pragma unroll
        for (int j = 0; j < 16; j++) {
            u64 hm = hcm[base + j];
            u64 ho = hco[base + j];
            aifm = fma2(hm, wif[j], aifm);
            agom = fma2(hm, wgo[j], agom);
            aifo = fma2(ho, wif[j], aifo);
            agoo = fma2(ho, wgo[j], agoo);
        }

        px[team][tw][0][lane] = aifo;
        px[team][tw][1][lane] = agoo;
        TEAM_BAR();
        u64 aif = add2(aifm, px[team][otw][0][lane]);
        u64 ago = add2(agom, px[team][otw][1][lane]);

        float zi, zf, zg, zo;
        upk2(aif, zi, zf); upk2(ago, zg, zo);
        h = cellf(zi, zf, zg, zo, cc);

        hds[team][cb ^ 1][tw][lane] = pk2(h, h);
        if (t < 125) cpa_wait<2>(); else cpa_wait<0>();
        TEAM_BAR();
    }

    // ---------------- zd = hT @ Wd + bd (warp-local, once) ----------------
    u64 zif = pk2(__ldg(bd + lane),      __ldg(bd + 32 + lane));
    u64 zgo = pk2(__ldg(bd + 64 + lane), __ldg(bd + 96 + lane));
    {
        float ht = h;
#pragma unroll
        for (int kk = 0; kk < 32; kk++) {
            float hv = __shfl_sync(0xffffffffu, ht, kk);
            const float* w = Wd + kk * 128;
            u64 hp = pk2(hv, hv);
            zif = fma2(hp, pk2(__ldg(w + lane),      __ldg(w + 32 + lane)), zif);
            zgo = fma2(hp, pk2(__ldg(w + 64 + lane), __ldg(w + 96 + lane)), zgo);
        }
    }

    // ---------------- decoder (reload U = Ud slice) ----------------
#pragma unroll
    for (int j = 0; j < 16; j++) {
        const float* u = Ud + (base + j) * 128;
        wif[j] = pk2(__ldg(u + lane),      __ldg(u + 32 + lane));
        wgo[j] = pk2(__ldg(u + 64 + lane), __ldg(u + 96 + lane));
    }

    hds[team][0][tw][lane] = 0ULL;
    hds[team][1][tw][lane] = 0ULL;
    TEAM_BAR();

    h = 0.f; cc = 0.f;
    u64 bo = pk2(__ldg(bout + lane), __ldg(bout + 32 + lane));
    float* y0 = y + (size_t)row * 128 * 64;

    for (int t = 0; t < 128; t++) {
        const int cb = t & 1;
        const u64* hcm = hds[team][cb][tw];
        const u64* hco = hds[team][cb][otw];

        u64 aifm = zif, agom = zgo, yam = bo;
        u64 aifo = 0ULL, agoo = 0ULL, yao = 0ULL;

#pragma unroll
        for (int j = 0; j < 16; j++) {
            u64 hm = hcm[base + j];
            u64 ho = hco[base + j];
            u64 wo = Wos[(base + j) * 32 + lane];
            aifm = fma2(hm, wif[j], aifm);
            agom = fma2(hm, wgo[j], agom);
            yam  = fma2(hm, wo, yam);
            aifo = fma2(ho, wif[j], aifo);
            agoo = fma2(ho, wgo[j], agoo);
            yao  = fma2(ho, wo, yao);
        }

        px[team][tw][0][lane] = aifo;
        px[team][tw][1][lane] = agoo;
        px[team][tw][2][lane] = yao;
        TEAM_BAR();
        u64 aif = add2(aifm, px[team][otw][0][lane]);
        u64 ago = add2(agom, px[team][otw][1][lane]);
        u64 ya  = add2(yam,  px[team][otw][2][lane]);

        if (t > 0) {   // ya used h_t = hs[t-1] -> y[t-1]
            float a, b;
            upk2(ya, a, b);
            y0[(size_t)(t - 1) * 64 + lane] = a;
            y0[(size_t)(t - 1) * 64 + 32 + lane] = b;
        }

        float zi, zf, zg, zo;
        upk2(aif, zi, zf); upk2(ago, zg, zo);
        h = cellf(zi, zf, zg, zo, cc);

        hds[team][cb ^ 1][tw][lane] = pk2(h, h);
        TEAM_BAR();
    }

    // epilogue: y[127] from h_128 (hds buf 0 after t=127; synced in-loop)
    {
        const u64* hcm = hds[team][0][tw];
        u64 ya0 = bo, ya1 = 0ULL;
#pragma unroll
        for (int kk = 0; kk < 32; kk += 2) {
            ya0 = fma2(hcm[kk],     Wos[kk * 32 + lane],       ya0);
            ya1 = fma2(hcm[kk + 1], Wos[(kk + 1) * 32 + lane], ya1);
        }
        u64 ya = add2(ya0, ya1);
        float a, b;
        upk2(ya, a, b);
        y0[(size_t)127 * 64 + lane] = a;
        y0[(size_t)127 * 64 + 32 + lane] = b;
    }
}

// =====================================================================
extern "C" void kernel_launch(void* const* d_in, const int* in_sizes, int n_in,
                              void* d_out, int out_size)
{
    const float* x    = (const float*)d_in[0];
    const float* We   = (const float*)d_in[1];
    const float* Ue   = (const float*)d_in[2];
    const float* be   = (const float*)d_in[3];
    const float* Wd   = (const float*)d_in[4];
    const float* Ud   = (const float*)d_in[5];
    const float* bd   = (const float*)d_in[6];
    const float* Wout = (const float*)d_in[7];
    const float* bout = (const float*)d_in[8];
    float* y = (float*)d_out;

    cudaFuncSetAttribute(k_xz, cudaFuncAttributeMaxDynamicSharedMemorySize, SMX_TOTAL);
    cudaFuncSetAttribute(k_xz, cudaFuncAttributePreferredSharedMemoryCarveout, 100);
    cudaFuncSetAttribute(k_rnn, cudaFuncAttributePreferredSharedMemoryCarveout, 100);

    k_xz<<<8192, 128, SMX_TOTAL>>>(x, We, be);
    k_rnn<<<1024, 128>>>(Ue, Ud, Wd, bd, Wout, bout, y);
}